// round 1
// baseline (speedup 1.0000x reference)
#include <cuda_runtime.h>
#include <cstdint>

#define FEAT_LEVELS 3
#define FEAT_DIM    8
#define TABLE       1048577
#define LAST_ROW    (TABLE - 1)

__global__ __launch_bounds__(256) void feature_octree_kernel(
    const float*  __restrict__ coord,     // (N, 3)
    const float*  __restrict__ features,  // (3, TABLE, 8)
    const int*    __restrict__ indices,   // (3, N, 8)
    float*        __restrict__ out,       // (N, 8)
    int n)
{
    int t = blockIdx.x * blockDim.x + threadIdx.x;
    if (t >= n) return;

    // coord load (3 floats, stride 12B)
    const float x = coord[3 * (size_t)t + 0];
    const float y = coord[3 * (size_t)t + 1];
    const float z = coord[3 * (size_t)t + 2];

    float acc0 = 0.f, acc1 = 0.f, acc2 = 0.f, acc3 = 0.f;
    float acc4 = 0.f, acc5 = 0.f, acc6 = 0.f, acc7 = 0.f;

    #pragma unroll
    for (int i = 0; i < FEAT_LEVELS; i++) {
        const int level = 12 - i;          // current_level
        const int fl    = 2 - i;           // feature_level
        // coords = 2^level * (x*0.5 + 0.5) = s*x + s with s = 2^(level-1)
        const float s = (float)(1 << (level - 1));

        float cx = fmaf(s, x, s);
        float cy = fmaf(s, y, s);
        float cz = fmaf(s, z, s);
        float dx = cx - floorf(cx);
        float dy = cy - floorf(cy);
        float dz = cz - floorf(cz);
        // smoothstep: 3d^2 - 2d^3
        dx = dx * dx * fmaf(-2.f, dx, 3.f);
        dy = dy * dy * fmaf(-2.f, dy, 3.f);
        dz = dz * dz * fmaf(-2.f, dz, 3.f);

        const float wx[2] = {1.f - dx, dx};
        const float wy[2] = {1.f - dy, dy};
        const float wz[2] = {1.f - dz, dz};

        // 8 contiguous int32 indices for this (level, point): two int4 loads
        const int4* ip = reinterpret_cast<const int4*>(
            indices + (size_t)i * n * 8 + (size_t)t * 8);
        const int4 ia = __ldg(ip);
        const int4 ib = __ldg(ip + 1);
        const int id[8] = {ia.x, ia.y, ia.z, ia.w, ib.x, ib.y, ib.z, ib.w};

        const float* fb = features + (size_t)fl * TABLE * FEAT_DIM;

        #pragma unroll
        for (int c = 0; c < 8; c++) {
            float w = wx[(c >> 2) & 1] * wy[(c >> 1) & 1] * wz[c & 1];
            // features[:, -1, :] is zeroed in the reference
            w = (id[c] == LAST_ROW) ? 0.f : w;
            const float4* g = reinterpret_cast<const float4*>(
                fb + (size_t)id[c] * FEAT_DIM);
            const float4 ga = __ldg(g);
            const float4 gb = __ldg(g + 1);
            acc0 = fmaf(w, ga.x, acc0);
            acc1 = fmaf(w, ga.y, acc1);
            acc2 = fmaf(w, ga.z, acc2);
            acc3 = fmaf(w, ga.w, acc3);
            acc4 = fmaf(w, gb.x, acc4);
            acc5 = fmaf(w, gb.y, acc5);
            acc6 = fmaf(w, gb.z, acc6);
            acc7 = fmaf(w, gb.w, acc7);
        }
    }

    float4* op = reinterpret_cast<float4*>(out + (size_t)t * FEAT_DIM);
    op[0] = make_float4(acc0, acc1, acc2, acc3);
    op[1] = make_float4(acc4, acc5, acc6, acc7);
}

extern "C" void kernel_launch(void* const* d_in, const int* in_sizes, int n_in,
                              void* d_out, int out_size)
{
    const float* coord    = (const float*)d_in[0];  // (N,3) float32
    const float* features = (const float*)d_in[1];  // (3,TABLE,8) float32
    const int*   indices  = (const int*)d_in[2];    // (3,N,8) int32
    float*       out      = (float*)d_out;          // (N,8) float32

    const int n = in_sizes[0] / 3;
    const int threads = 256;
    const int blocks = (n + threads - 1) / threads;
    feature_octree_kernel<<<blocks, threads>>>(coord, features, indices, out, n);
}

// round 3
// speedup vs baseline: 1.0324x; 1.0324x over previous
#include <cuda_runtime.h>
#include <cstdint>

#define FEAT_DIM  8
#define TABLE     1048577
#define LAST_ROW  (TABLE - 1)

// One warp handles 4 points; 8 lanes per point, one lane per feature dim.
// Gather LDG.32: 4 lane-groups hit 4 distinct 32B rows -> 4 full-width
// wavefronts instead of 32 quarter-width ones.
template <bool FIRST>
__global__ __launch_bounds__(256) void octree_level_kernel(
    const float* __restrict__ coord,   // (N,3)
    const float* __restrict__ feat,    // (TABLE,8) for this level
    const int*   __restrict__ idx,     // (N,8) for this level
    float*       __restrict__ out,     // (N,8)
    int n, float s)                    // s = 2^(level-1)
{
    const int lane = threadIdx.x & 31;
    const int gwarp = (blockIdx.x * blockDim.x + threadIdx.x) >> 5;
    const int dim  = lane & 7;          // feature component this lane owns
    const int p0   = gwarp * 4 + (lane >> 3);
    const bool valid = (p0 < n);
    const int p = valid ? p0 : (n > 0 ? n - 1 : 0); // clamp: full-warp shuffles stay legal

    // interpolation weights for this point (redundant across the 8 lanes)
    const float x = __ldcs(&coord[3 * (size_t)p + 0]);
    const float y = __ldcs(&coord[3 * (size_t)p + 1]);
    const float z = __ldcs(&coord[3 * (size_t)p + 2]);
    float cx = fmaf(s, x, s), cy = fmaf(s, y, s), cz = fmaf(s, z, s);
    float dx = cx - floorf(cx), dy = cy - floorf(cy), dz = cz - floorf(cz);
    dx = dx * dx * fmaf(-2.f, dx, 3.f);   // smoothstep 3d^2-2d^3
    dy = dy * dy * fmaf(-2.f, dy, 3.f);
    dz = dz * dz * fmaf(-2.f, dz, 3.f);

    // my corner index: lane (sub*8 + c) holds idx[p][c]; dim doubles as c here.
    // Warp-wide this is a single fully-coalesced 128B read.
    const int myidx = __ldcs(&idx[(size_t)p * 8 + dim]);

    float acc;
    if (FIRST) acc = 0.f;
    else       acc = __ldcs(&out[(size_t)p * 8 + dim]);

    const int base = lane & 24;         // first lane of my 8-lane subgroup

    #pragma unroll
    for (int c = 0; c < 8; c++) {
        const int ic = __shfl_sync(0xffffffffu, myidx, base | c);
        float w = ((c & 4) ? dx : 1.f - dx)
                * ((c & 2) ? dy : 1.f - dy)
                * ((c & 1) ? dz : 1.f - dz);
        if (ic == LAST_ROW) w = 0.f;    // features[:, -1, :] zeroed in reference
        const float f = __ldg(&feat[(size_t)ic * FEAT_DIM + dim]);
        acc = fmaf(w, f, acc);
    }

    if (valid) out[(size_t)p * 8 + dim] = acc;
}

extern "C" void kernel_launch(void* const* d_in, const int* in_sizes, int n_in,
                              void* d_out, int out_size)
{
    const float* coord    = (const float*)d_in[0];  // (N,3)
    const float* features = (const float*)d_in[1];  // (3,TABLE,8)
    const int*   indices  = (const int*)d_in[2];    // (3,N,8)
    float*       out      = (float*)d_out;          // (N,8)

    const int n = in_sizes[0] / 3;
    const int threads = 256;
    const int blocks = (n + 31) / 32;   // 32 points per block (8 warps x 4)

    // pass i: indices[i] pairs with features[2-i], level = 12-i, s = 2^(level-1)
    // One table (33.5 MB) per pass -> gathers stay L2-resident.
    octree_level_kernel<true><<<blocks, threads>>>(
        coord, features + (size_t)2 * TABLE * FEAT_DIM,
        indices + (size_t)0 * n * 8, out, n, 2048.f);
    octree_level_kernel<false><<<blocks, threads>>>(
        coord, features + (size_t)1 * TABLE * FEAT_DIM,
        indices + (size_t)1 * n * 8, out, n, 1024.f);
    octree_level_kernel<false><<<blocks, threads>>>(
        coord, features + (size_t)0 * TABLE * FEAT_DIM,
        indices + (size_t)2 * n * 8, out, n, 512.f);
}

// round 5
// speedup vs baseline: 1.0565x; 1.0233x over previous
#include <cuda_runtime.h>
#include <cstdint>

#define FEAT_DIM  8
#define TABLE     1048577
#define LAST_ROW  (TABLE - 1)

// One warp handles 4 points; 8 lanes per point, one lane per feature dim.
// Each lane precomputes the weight + byte-offset for exactly ONE corner
// (its dim index doubles as the corner id), stages it in smem, then the
// inner loop is just LDS.64(broadcast) + LDG + FFMA per corner.
template <bool FIRST>
__global__ __launch_bounds__(256) void octree_level_kernel(
    const float* __restrict__ coord,   // (N,3)
    const float* __restrict__ feat,    // (TABLE,8) for this level
    const int*   __restrict__ idx,     // (N,8) for this level
    float*       __restrict__ out,     // (N,8)
    int n, float s)                    // s = 2^(level-1)
{
    __shared__ float2 stage[8][4][8];  // [warp][sub-point][corner] = (w, off_bits)

    const int lane = threadIdx.x & 31;
    const int wid  = threadIdx.x >> 5;
    const int dim  = lane & 7;          // feature component AND corner id
    const int sub  = lane >> 3;         // which of the warp's 4 points
    const int gwarp = (blockIdx.x * blockDim.x + threadIdx.x) >> 5;
    const int p0   = gwarp * 4 + sub;
    const bool valid = (p0 < n);
    const int p = valid ? p0 : (n > 0 ? n - 1 : 0);

    // interpolation fractions for this point
    const float x = __ldcs(&coord[3 * (size_t)p + 0]);
    const float y = __ldcs(&coord[3 * (size_t)p + 1]);
    const float z = __ldcs(&coord[3 * (size_t)p + 2]);
    float cx = fmaf(s, x, s), cy = fmaf(s, y, s), cz = fmaf(s, z, s);
    float dx = cx - floorf(cx), dy = cy - floorf(cy), dz = cz - floorf(cz);
    dx = dx * dx * fmaf(-2.f, dx, 3.f);   // smoothstep 3d^2-2d^3
    dy = dy * dy * fmaf(-2.f, dy, 3.f);
    dz = dz * dz * fmaf(-2.f, dz, 3.f);

    // weight for MY corner only (corner c = dim): bit2->x, bit1->y, bit0->z
    float w = ((dim & 4) ? dx : 1.f - dx)
            * ((dim & 2) ? dy : 1.f - dy)
            * ((dim & 1) ? dz : 1.f - dz);

    // my corner's table index: warp-wide this is one coalesced 128B read
    const int myidx = __ldcs(&idx[(size_t)p * 8 + dim]);
    if (myidx == LAST_ROW) w = 0.f;     // features[:, -1, :] zeroed in reference
    const unsigned off = (unsigned)myidx * (FEAT_DIM * 4u);   // byte offset, < 34MB

    stage[wid][sub][dim] = make_float2(w, __uint_as_float(off));
    __syncwarp();

    const char* fb = (const char*)feat + dim * 4;
    float acc;
    if (FIRST) acc = 0.f;
    else       acc = __ldcs(&out[(size_t)p * 8 + dim]);

    #pragma unroll
    for (int c = 0; c < 8; c++) {
        const float2 e = stage[wid][sub][c];          // broadcast LDS.64
        const float f = __ldg(reinterpret_cast<const float*>(
                                  fb + __float_as_uint(e.y)));
        acc = fmaf(e.x, f, acc);
    }

    if (valid) out[(size_t)p * 8 + dim] = acc;
}

extern "C" void kernel_launch(void* const* d_in, const int* in_sizes, int n_in,
                              void* d_out, int out_size)
{
    const float* coord    = (const float*)d_in[0];  // (N,3)
    const float* features = (const float*)d_in[1];  // (3,TABLE,8)
    const int*   indices  = (const int*)d_in[2];    // (3,N,8)
    float*       out      = (float*)d_out;          // (N,8)

    const int n = in_sizes[0] / 3;
    const int threads = 256;
    const int blocks = (n + 31) / 32;   // 32 points per block (8 warps x 4)

    // pass i: indices[i] pairs with features[2-i], level = 12-i, s = 2^(level-1)
    // One table (33.5 MB) per pass -> gathers stay L2-resident.
    octree_level_kernel<true><<<blocks, threads>>>(
        coord, features + (size_t)2 * TABLE * FEAT_DIM,
        indices + (size_t)0 * n * 8, out, n, 2048.f);
    octree_level_kernel<false><<<blocks, threads>>>(
        coord, features + (size_t)1 * TABLE * FEAT_DIM,
        indices + (size_t)1 * n * 8, out, n, 1024.f);
    octree_level_kernel<false><<<blocks, threads>>>(
        coord, features + (size_t)0 * TABLE * FEAT_DIM,
        indices + (size_t)2 * n * 8, out, n, 512.f);
}

// round 7
// speedup vs baseline: 1.2872x; 1.2184x over previous
#include <cuda_runtime.h>
#include <cstdint>

#define FEAT_DIM  8
#define TABLE     1048577
#define LAST_ROW  (TABLE - 1)

// 2 lanes per point; each lane owns 16B (4 dims) of every gathered 32B row.
// Per corner: 1 LDG.128 brings the lane's half-row; the warp instruction
// covers 16 points -> 16 distinct lines -> same wavefront count as before
// but ~3x fewer issued instructions per point.
template <bool FIRST>
__global__ __launch_bounds__(256) void octree_level_kernel(
    const float* __restrict__ coord,   // (N,3)
    const float* __restrict__ feat,    // (TABLE,8) for this level
    const int*   __restrict__ idx,     // (N,8) for this level
    float*       __restrict__ out,     // (N,8)
    int n, float s)                    // s = 2^(level-1)
{
    const int lane  = threadIdx.x & 31;
    const int gwarp = (blockIdx.x * blockDim.x + threadIdx.x) >> 5;
    const int half  = lane & 1;                 // which 16B half of the row
    const int p0    = gwarp * 16 + (lane >> 1);
    const bool valid = (p0 < n);
    const int p = valid ? p0 : (n > 0 ? n - 1 : 0);

    // interpolation fractions (lane pairs duplicate; loads are coalesced-ish)
    const float x = __ldcs(&coord[3 * (size_t)p + 0]);
    const float y = __ldcs(&coord[3 * (size_t)p + 1]);
    const float z = __ldcs(&coord[3 * (size_t)p + 2]);
    float cx = fmaf(s, x, s), cy = fmaf(s, y, s), cz = fmaf(s, z, s);
    float dx = cx - floorf(cx), dy = cy - floorf(cy), dz = cz - floorf(cz);
    dx = dx * dx * fmaf(-2.f, dx, 3.f);   // smoothstep 3d^2-2d^3
    dy = dy * dy * fmaf(-2.f, dy, 3.f);
    dz = dz * dz * fmaf(-2.f, dz, 3.f);

    const float ex = 1.f - dx, ey = 1.f - dy, ez = 1.f - dz;
    // corner weights, bit2->x, bit1->y, bit0->z
    const float exey = ex * ey, exdy = ex * dy, dxey = dx * ey, dxdy = dx * dy;
    float w[8];
    w[0] = exey * ez; w[1] = exey * dz;
    w[2] = exdy * ez; w[3] = exdy * dz;
    w[4] = dxey * ez; w[5] = dxey * dz;
    w[6] = dxdy * ez; w[7] = dxdy * dz;

    // this point's 8 indices (lane pairs read the same 32B: L1 broadcast)
    const int4* ip = reinterpret_cast<const int4*>(idx + (size_t)p * 8);
    const int4 ia = __ldcs(ip);
    const int4 ib = __ldcs(ip + 1);
    const int id[8] = {ia.x, ia.y, ia.z, ia.w, ib.x, ib.y, ib.z, ib.w};

    const char* fb = (const char*)feat + half * 16;   // my 16B half
    float a0, a1, a2, a3;
    if (FIRST) { a0 = a1 = a2 = a3 = 0.f; }
    else {
        const float4 prev = __ldcs(reinterpret_cast<const float4*>(
            out + (size_t)p * 8 + half * 4));
        a0 = prev.x; a1 = prev.y; a2 = prev.z; a3 = prev.w;
    }

    #pragma unroll
    for (int c = 0; c < 8; c++) {
        float wc = (id[c] == LAST_ROW) ? 0.f : w[c];  // features[:,-1,:]=0
        const float4 g = __ldg(reinterpret_cast<const float4*>(
            fb + (size_t)(unsigned)id[c] * 32u));
        a0 = fmaf(wc, g.x, a0);
        a1 = fmaf(wc, g.y, a1);
        a2 = fmaf(wc, g.z, a2);
        a3 = fmaf(wc, g.w, a3);
    }

    if (valid) {
        float4* op = reinterpret_cast<float4*>(out + (size_t)p * 8 + half * 4);
        *op = make_float4(a0, a1, a2, a3);
    }
}

extern "C" void kernel_launch(void* const* d_in, const int* in_sizes, int n_in,
                              void* d_out, int out_size)
{
    const float* coord    = (const float*)d_in[0];  // (N,3)
    const float* features = (const float*)d_in[1];  // (3,TABLE,8)
    const int*   indices  = (const int*)d_in[2];    // (3,N,8)
    float*       out      = (float*)d_out;          // (N,8)

    const int n = in_sizes[0] / 3;
    const int threads = 256;
    const int blocks = (n + 127) / 128;  // 128 points/block (8 warps x 16)

    // pass i: indices[i] pairs with features[2-i], level = 12-i, s = 2^(level-1)
    // One table (33.5 MB) per pass -> gathers stay L2-resident.
    octree_level_kernel<true><<<blocks, threads>>>(
        coord, features + (size_t)2 * TABLE * FEAT_DIM,
        indices + (size_t)0 * n * 8, out, n, 2048.f);
    octree_level_kernel<false><<<blocks, threads>>>(
        coord, features + (size_t)1 * TABLE * FEAT_DIM,
        indices + (size_t)1 * n * 8, out, n, 1024.f);
    octree_level_kernel<false><<<blocks, threads>>>(
        coord, features + (size_t)0 * TABLE * FEAT_DIM,
        indices + (size_t)2 * n * 8, out, n, 512.f);
}